// round 3
// baseline (speedup 1.0000x reference)
#include <cuda_runtime.h>
#include <stdint.h>

#define B_      8
#define IN_CH   64
#define OUT_CH  64
#define GROUPS  8
#define FPG     8      // input channels per group
#define OPG     8      // output channels per group
#define H_      256
#define W_      256
#define KS      3

#define TX      64     // tile width (output px)
#define TY      16     // tile height
#define HX      (TX + 2)
#define HY      (TY + 2)

// Per-sample dynamic kernels: [b][oc][ky*3+kx]
__device__ float g_kern[B_ * OUT_CH * KS * KS];

// k[b,j] = leakyrelu( sum_i rep[b,i] * W[j,i], 0.1 ),  j in [0, 576)
__global__ void gen_kernels(const float* __restrict__ rep,
                            const float* __restrict__ Wm) {
    int b = blockIdx.x;
    int j = threadIdx.x;
    if (j >= OUT_CH * KS * KS) return;
    const float* r = rep + b * 32;
    const float* w = Wm + j * 32;
    float s = 0.f;
#pragma unroll
    for (int i = 0; i < 32; i++) s = fmaf(r[i], w[i], s);
    g_kern[b * (OUT_CH * KS * KS) + j] = (s > 0.f) ? s : 0.1f * s;
}

// One block: (b, g, 64x16 output tile). Sum 8 input channels of the group
// into smem (with reflect-padded halo), then 3x3 conv -> 8 output channels.
__global__ __launch_bounds__(256, 8)
void dynconv_kernel(const float* __restrict__ x, float* __restrict__ out) {
    __shared__ float s[HY][HX];          // 18 x 66 = 1188 floats
    __shared__ float kw[OPG][9];

    const int bg = blockIdx.z;           // 0..63
    const int b  = bg >> 3;
    const int g  = bg & 7;
    const int tx0 = blockIdx.x * TX;
    const int ty0 = blockIdx.y * TY;
    const int tid = threadIdx.x;         // 0..255

    // dynamic kernel weights for this (b, group): 8 oc x 9 taps
    if (tid < OPG * 9) {
        int oc = g * OPG + tid / 9;
        kw[tid / 9][tid % 9] = g_kern[(b * OUT_CH + oc) * 9 + tid % 9];
    }

    const size_t plane = (size_t)H_ * W_;
    const float* xg = x + ((size_t)b * IN_CH + (size_t)g * FPG) * plane;

    // Load halo: reflect-pad coords, sum the 8 channels of the group.
    for (int i = tid; i < HY * HX; i += 256) {
        int hy = i / HX, hx = i - hy * HX;
        int gy = ty0 + hy - 1;
        int gx = tx0 + hx - 1;
        gy = (gy < 0) ? -gy : ((gy >= H_) ? 2 * H_ - 2 - gy : gy);
        gx = (gx < 0) ? -gx : ((gx >= W_) ? 2 * W_ - 2 - gx : gx);
        const float* p = xg + (size_t)gy * W_ + gx;
        float acc = 0.f;
#pragma unroll
        for (int c = 0; c < FPG; c++) acc += p[c * plane];
        s[hy][hx] = acc;
    }
    __syncthreads();

    // Each thread: column px, 4 rows (py, py+4, py+8, py+12), 8 ocs each.
    const int px = tid & 63;
    const int py = tid >> 6;             // 0..3
    float* ob = out + ((size_t)b * OUT_CH + (size_t)g * OPG) * plane
                    + (size_t)ty0 * W_ + tx0 + px;

#pragma unroll
    for (int r = 0; r < 4; r++) {
        const int yy = py + r * 4;       // row within tile
        float t[9];
#pragma unroll
        for (int dy = 0; dy < 3; dy++)
#pragma unroll
            for (int dx = 0; dx < 3; dx++)
                t[dy * 3 + dx] = s[yy + dy][px + dx];

#pragma unroll
        for (int oc = 0; oc < OPG; oc++) {
            float acc = 0.f;
#pragma unroll
            for (int k = 0; k < 9; k++) acc = fmaf(t[k], kw[oc][k], acc);
            ob[(size_t)oc * plane + (size_t)yy * W_] = acc;
        }
    }
}

extern "C" void kernel_launch(void* const* d_in, const int* in_sizes, int n_in,
                              void* d_out, int out_size) {
    const float* x   = (const float*)d_in[0];
    const float* rep = (const float*)d_in[1];
    const float* Wm  = (const float*)d_in[2];
    float* out = (float*)d_out;

    gen_kernels<<<B_, OUT_CH * KS * KS>>>(rep, Wm);

    dim3 grid(W_ / TX, H_ / TY, B_ * GROUPS);   // 4 x 16 x 64
    dynconv_kernel<<<grid, 256>>>(x, out);
}

// round 7
// speedup vs baseline: 3.0204x; 3.0204x over previous
#include <cuda_runtime.h>
#include <stdint.h>

#define B_      8
#define IN_CH   64
#define OUT_CH  64
#define GROUPS  8
#define FPG     8
#define OPG     8
#define H_      256
#define W_      256
#define KS      3

#define TY      16           // output rows per block
#define HY      (TY + 2)     // halo rows
#define SW      264          // smem row width (floats): 4 pad | 256 | 4 pad -> 16B aligned rows

// Per-sample dynamic kernels: [b][oc][ky*3+kx]
__device__ float g_kern[B_ * OUT_CH * KS * KS];

__global__ void gen_kernels(const float* __restrict__ rep,
                            const float* __restrict__ Wm) {
    int b = blockIdx.x;
    int j = threadIdx.x;
    if (j >= OUT_CH * KS * KS) return;
    const float* r = rep + b * 32;
    const float* w = Wm + j * 32;
    float s = 0.f;
#pragma unroll
    for (int i = 0; i < 32; i++) s = fmaf(r[i], w[i], s);
    g_kern[b * (OUT_CH * KS * KS) + j] = (s > 0.f) ? s : 0.1f * s;
}

// Block = (b, g, 16-row full-width stripe). Sum the group's 8 input channels
// into smem with reflect halo (float4, fully aligned), then 3x3 conv -> 8 oc.
__global__ __launch_bounds__(256, 8)
void dynconv_kernel(const float* __restrict__ x, float* __restrict__ out) {
    __shared__ float S[HY][SW];       // 18 x 264 x 4B = 19008 B
    __shared__ float kw[OPG][9];

    const int bg  = blockIdx.y;       // 0..63
    const int b   = bg >> 3;
    const int g   = bg & 7;
    const int ty0 = blockIdx.x * TY;
    const int tid = threadIdx.x;      // 0..255

    if (tid < OPG * 9) {
        int oc = g * OPG + tid / 9;
        kw[tid / 9][tid % 9] = g_kern[(b * OUT_CH + oc) * 9 + tid % 9];
    }

    const size_t plane = (size_t)H_ * W_;
    const float* xg = x + ((size_t)b * IN_CH + (size_t)g * FPG) * plane;

    // Interior halo: 18 rows x 64 float4 quads, all 16B-aligned, full rows.
    for (int q = tid; q < HY * 64; q += 256) {
        const int hy = q >> 6;
        const int qx = q & 63;
        int gy = ty0 + hy - 1;
        gy = (gy < 0) ? -gy : ((gy >= H_) ? 2 * H_ - 2 - gy : gy);
        const float4* p = (const float4*)(xg + (size_t)gy * W_) + qx;
        float4 a = make_float4(0.f, 0.f, 0.f, 0.f);
#pragma unroll
        for (int c = 0; c < FPG; c++) {
            float4 v = p[c * (plane / 4)];
            a.x += v.x; a.y += v.y; a.z += v.z; a.w += v.w;
        }
        *(float4*)&S[hy][4 + qx * 4] = a;
    }

    // Edge columns: gx=-1 reflects to 1, gx=256 reflects to 254 (both interior
    // addresses, L1-hot). 36 threads, scalar.
    if (tid < HY * 2) {
        const int hy   = tid >> 1;
        const int side = tid & 1;
        int gy = ty0 + hy - 1;
        gy = (gy < 0) ? -gy : ((gy >= H_) ? 2 * H_ - 2 - gy : gy);
        const int gx = side ? (W_ - 2) : 1;
        const float* p = xg + (size_t)gy * W_ + gx;
        float a = 0.f;
#pragma unroll
        for (int c = 0; c < FPG; c++) a += p[c * plane];
        S[hy][side ? (4 + W_) : 3] = a;
    }
    __syncthreads();

    // Compute: thread owns one column (px = tid), slides 3-tap rows down.
    const int px = tid;
    float* ob = out + ((size_t)b * OUT_CH + (size_t)g * OPG) * plane
                    + (size_t)ty0 * W_ + px;

    float t0a = S[0][px + 3], t0b = S[0][px + 4], t0c = S[0][px + 5];
    float t1a = S[1][px + 3], t1b = S[1][px + 4], t1c = S[1][px + 5];

#pragma unroll
    for (int yy = 0; yy < TY; yy++) {
        const float t2a = S[yy + 2][px + 3];
        const float t2b = S[yy + 2][px + 4];
        const float t2c = S[yy + 2][px + 5];

#pragma unroll
        for (int oc = 0; oc < OPG; oc++) {
            float acc;
            acc = t0a * kw[oc][0];
            acc = fmaf(t0b, kw[oc][1], acc);
            acc = fmaf(t0c, kw[oc][2], acc);
            acc = fmaf(t1a, kw[oc][3], acc);
            acc = fmaf(t1b, kw[oc][4], acc);
            acc = fmaf(t1c, kw[oc][5], acc);
            acc = fmaf(t2a, kw[oc][6], acc);
            acc = fmaf(t2b, kw[oc][7], acc);
            acc = fmaf(t2c, kw[oc][8], acc);
            ob[(size_t)oc * plane + (size_t)yy * W_] = acc;
        }

        t0a = t1a; t0b = t1b; t0c = t1c;
        t1a = t2a; t1b = t2b; t1c = t2c;
    }
}

extern "C" void kernel_launch(void* const* d_in, const int* in_sizes, int n_in,
                              void* d_out, int out_size) {
    const float* x   = (const float*)d_in[0];
    const float* rep = (const float*)d_in[1];
    const float* Wm  = (const float*)d_in[2];
    float* out = (float*)d_out;

    gen_kernels<<<B_, OUT_CH * KS * KS>>>(rep, Wm);

    dim3 grid(H_ / TY, B_ * GROUPS);   // 16 x 64 = 1024 blocks
    dynconv_kernel<<<grid, 256>>>(x, out);
}

// round 9
// speedup vs baseline: 3.6696x; 1.2150x over previous
#include <cuda_runtime.h>
#include <stdint.h>

#define B_      8
#define IN_CH   64
#define OUT_CH  64
#define GROUPS  8
#define FPG     8
#define OPG     8
#define H_      256
#define W_      256

#define TY      16           // output rows per block
#define HY      (TY + 2)     // halo rows
#define SW      264          // smem row: 4 pad | 256 | 4 pad (16B-aligned rows)

// One fused kernel. Block = (b, g, 16-row full-width stripe).
//  - threads 128..199 compute this (b,g)'s 72 dynamic weights (linear+leaky)
//  - all threads sum the group's 8 input channels into smem w/ reflect halo
//  - compute: each thread owns 4 columns x 4 rows, 8 output channels,
//    float4 stores.
__global__ __launch_bounds__(256, 7)
void dynconv_fused(const float* __restrict__ x,
                   const float* __restrict__ rep,
                   const float* __restrict__ Wm,
                   float* __restrict__ out) {
    __shared__ float S[HY][SW];       // 18 x 264 x 4B = 19008 B
    __shared__ float kw[OPG][9];

    const int bg  = blockIdx.y;       // 0..63
    const int b   = bg >> 3;
    const int g   = bg & 7;
    const int ty0 = blockIdx.x * TY;
    const int tid = threadIdx.x;      // 0..255

    const size_t plane = (size_t)H_ * W_;
    const float* xg = x + ((size_t)b * IN_CH + (size_t)g * FPG) * plane;

    // ---- interior halo: 18 rows x 64 aligned float4 quads, 8-ch sum ----
    for (int q = tid; q < HY * 64; q += 256) {
        const int hy = q >> 6;
        const int qx = q & 63;
        int gy = ty0 + hy - 1;
        gy = (gy < 0) ? -gy : ((gy >= H_) ? 2 * H_ - 2 - gy : gy);
        const float4* p = (const float4*)(xg + (size_t)gy * W_) + qx;
        float4 a = p[0];
#pragma unroll
        for (int c = 1; c < FPG; c++) {
            float4 v = p[c * (plane / 4)];
            a.x += v.x; a.y += v.y; a.z += v.z; a.w += v.w;
        }
        *(float4*)&S[hy][4 + qx * 4] = a;
    }

    // ---- dynamic weights for this (b,g): threads 128..199 ----
    if (tid >= 128 && tid < 128 + OPG * 9) {
        const int j   = tid - 128;        // 0..71
        const int ocl = j / 9;
        const int tap = j - ocl * 9;
        const float4* r = (const float4*)(rep + b * 32);
        const float4* w = (const float4*)(Wm + ((size_t)((g * OPG + ocl) * 9 + tap)) * 32);
        float s = 0.f;
#pragma unroll
        for (int i = 0; i < 8; i++) {
            float4 rv = r[i], wv = w[i];
            s = fmaf(rv.x, wv.x, s);
            s = fmaf(rv.y, wv.y, s);
            s = fmaf(rv.z, wv.z, s);
            s = fmaf(rv.w, wv.w, s);
        }
        kw[ocl][tap] = (s > 0.f) ? s : 0.1f * s;
    }

    // ---- edge columns (reflect x): gx=-1 -> 1, gx=256 -> 254 ----
    if (tid >= 200 && tid < 200 + 2 * HY) {
        const int e    = tid - 200;
        const int hy   = e >> 1;
        const int side = e & 1;
        int gy = ty0 + hy - 1;
        gy = (gy < 0) ? -gy : ((gy >= H_) ? 2 * H_ - 2 - gy : gy);
        const float* p = xg + (size_t)gy * W_ + (side ? (W_ - 2) : 1);
        float a = 0.f;
#pragma unroll
        for (int c = 0; c < FPG; c++) a += p[c * plane];
        S[hy][side ? (4 + W_) : 3] = a;
    }
    __syncthreads();

    // ---- compute: thread owns 4 columns (px0..px0+3) x 4 rows x 8 oc ----
    const int c   = tid & 63;         // column quad
    const int r4  = tid >> 6;         // row group 0..3
    const int px0 = c * 4;
    const int y0  = r4 * 4;

    float* ob = out + ((size_t)b * OUT_CH + (size_t)g * OPG) * plane
                    + (size_t)(ty0 + y0) * W_ + px0;

    // sliding 3-row window of 6 taps each (smem cols 3+px0 .. 8+px0)
    float w0[6], w1[6], w2[6];
#pragma unroll
    for (int k = 0; k < 6; k++) w0[k] = S[y0][3 + px0 + k];
#pragma unroll
    for (int k = 0; k < 6; k++) w1[k] = S[y0 + 1][3 + px0 + k];

#pragma unroll
    for (int rr = 0; rr < 4; rr++) {
#pragma unroll
        for (int k = 0; k < 6; k++) w2[k] = S[y0 + rr + 2][3 + px0 + k];

#pragma unroll
        for (int oc = 0; oc < OPG; oc++) {
            const float k0 = kw[oc][0], k1 = kw[oc][1], k2 = kw[oc][2];
            const float k3 = kw[oc][3], k4 = kw[oc][4], k5 = kw[oc][5];
            const float k6 = kw[oc][6], k7 = kw[oc][7], k8 = kw[oc][8];
            float4 v;
#pragma unroll
            for (int j = 0; j < 4; j++) {
                float a;
                a = w0[j] * k0;
                a = fmaf(w0[j + 1], k1, a);
                a = fmaf(w0[j + 2], k2, a);
                a = fmaf(w1[j],     k3, a);
                a = fmaf(w1[j + 1], k4, a);
                a = fmaf(w1[j + 2], k5, a);
                a = fmaf(w2[j],     k6, a);
                a = fmaf(w2[j + 1], k7, a);
                a = fmaf(w2[j + 2], k8, a);
                ((float*)&v)[j] = a;
            }
            *(float4*)(ob + (size_t)oc * plane + (size_t)rr * W_) = v;
        }

#pragma unroll
        for (int k = 0; k < 6; k++) { w0[k] = w1[k]; w1[k] = w2[k]; }
    }
}

extern "C" void kernel_launch(void* const* d_in, const int* in_sizes, int n_in,
                              void* d_out, int out_size) {
    const float* x   = (const float*)d_in[0];
    const float* rep = (const float*)d_in[1];
    const float* Wm  = (const float*)d_in[2];
    float* out = (float*)d_out;

    dim3 grid(H_ / TY, B_ * GROUPS);   // 16 x 64 = 1024 blocks, single wave
    dynconv_fused<<<grid, 256>>>(x, rep, Wm, out);
}